// round 16
// baseline (speedup 1.0000x reference)
#include <cuda_runtime.h>
#include <math.h>

#define MARGIN 0.2f
#define EPS_V  1e-6f

// Packed accumulator: bits[0:38) sum_q (fixed-point 2^16),
//                     bits[38:52) valid count, bits[52:64) done-block count.
#define CNT_SHIFT  38
#define DONE_SHIFT 52
#define SUM_MASK   ((1ull << CNT_SHIFT) - 1ull)
#define CNT_MASK   ((1ull << (DONE_SHIFT - CNT_SHIFT)) - 1ull)

// Only global state: zero-init at load; last block resets it each run.
__device__ unsigned long long g_acc;

__device__ __forceinline__ unsigned long long quant(float per) {
    return (unsigned long long)(unsigned int)(per * 65536.0f + 0.5f);
}

// ---------------------------------------------------------------------------
// Warp-collective: first j with label[j] != l0 (or -1 -> all same).
// ---------------------------------------------------------------------------
__device__ __forceinline__ int warp_find_first_diff(const int* __restrict__ label,
                                                    int B, int lane, int l0) {
    for (int base = 0; base < B; base += 128) {
        const int j0 = base + (lane << 2);
        unsigned sub = 0u;
        if (j0 + 3 < B) {
            int4 lv = *(const int4*)(label + j0);
            sub = (lv.x != l0 ? 1u : 0u) | (lv.y != l0 ? 2u : 0u)
                | (lv.z != l0 ? 4u : 0u) | (lv.w != l0 ? 8u : 0u);
        } else {
            #pragma unroll
            for (int t = 0; t < 4; t++) {
                int j = j0 + t;
                if (j < B && label[j] != l0) sub |= 1u << t;
            }
        }
        unsigned act = __ballot_sync(0xffffffffu, sub != 0u);
        if (act) {
            int src = __ffs(act) - 1;
            unsigned ssub = __shfl_sync(0xffffffffu, sub, src);
            return base + (src << 2) + (__ffs(ssub) - 1);
        }
    }
    return -1;
}

// ---------------------------------------------------------------------------
// Warp-collective: first j with label[j]==lab_i && zidx[j]!=idx_i (or -1).
// ---------------------------------------------------------------------------
__device__ __forceinline__ int warp_find_pos(const int* __restrict__ label,
                                             const int* __restrict__ zidx,
                                             int B, int lane, int lab_i, int idx_i) {
    for (int base = 0; base < B; base += 128) {
        const int j0 = base + (lane << 2);
        unsigned sub = 0u;
        if (j0 + 3 < B) {
            int4 lv = *(const int4*)(label + j0);
            sub = (lv.x == lab_i ? 1u : 0u) | (lv.y == lab_i ? 2u : 0u)
                | (lv.z == lab_i ? 4u : 0u) | (lv.w == lab_i ? 8u : 0u);
        } else {
            #pragma unroll
            for (int t = 0; t < 4; t++) {
                int j = j0 + t;
                if (j < B && label[j] == lab_i) sub |= 1u << t;
            }
        }
        while (true) {
            unsigned act = __ballot_sync(0xffffffffu, sub != 0u);
            if (!act) break;
            int src = __ffs(act) - 1;
            unsigned ssub = __shfl_sync(0xffffffffu, sub, src);
            int j = base + (src << 2) + (__ffs(ssub) - 1);
            if (__ldg(&zidx[j]) != idx_i) return j;   // broadcast load
            if (lane == src) sub &= (sub - 1u);
        }
    }
    return -1;
}

// ---------------------------------------------------------------------------
// Fast path (C==1024): 4 rows per block, TWO warps per row (one half-row
// each). Even warp mines pos/neg for the row (odd warp's a-prefetch overlaps
// it). Row 0 (neg for ~255/256 rows) staged in SMEM. Halves combine partial
// sums in SMEM. ~40 regs -> 6 blocks/SM; a full row still has 8 LDG.128 in
// flight (across its two warps) + 8 batched pos loads.
// Tail = one packed relaxed atomicAdd per block (no fences -> no L1 flush).
// ---------------------------------------------------------------------------
__global__ void __launch_bounds__(256, 6) triplet_kernel(const float* __restrict__ z,
                                                         const int* __restrict__ label,
                                                         const int* __restrict__ zidx,
                                                         float* __restrict__ out,
                                                         int B, int C, int k,
                                                         unsigned int nblocks) {
    __shared__ float4 s_n4[256];          // row 0 staging (4 KB)
    __shared__ int    s_pos[4], s_neg[4];
    __shared__ float  s_sap[8], s_san[8];
    __shared__ unsigned long long s_q[8];
    __shared__ unsigned int      s_c[8];

    const int tid  = threadIdx.x;
    const int warp = tid >> 5;
    const int lane = tid & 31;
    const bool fast = (C == 1024);

    if (fast) {
        const int rid = warp >> 1;             // row slot 0..3
        const int h   = warp & 1;              // half 0/1
        const int i   = blockIdx.x * 4 + rid;  // global row
        const int base = (h << 7);             // float4 offset of this half

        // ---- stage row 0 (neg) + prefetch this warp's a-half ----
        s_n4[tid] = __ldg(&((const float4*)z)[tid]);
        float4 av[4];
        if (i < B) {
            const float4* a = (const float4*)(z + (size_t)i * 1024);
            #pragma unroll
            for (int u = 0; u < 4; u++)
                av[u] = a[base + lane + (u << 5)];
        }

        // ---- even warp mines its row (overlaps all prefetches) ----
        if (h == 0) {
            if (i < B) {
                const int l0    = __ldg(&label[0]);
                const int lab_i = __ldg(&label[i]);
                const int idx_i = __ldg(&zidx[i]);
                int pos = -1, neg = -1;
                bool closed = false;
                if (lab_i != l0) {
                    neg = 0;
                } else {
                    neg = warp_find_first_diff(label, B, lane, l0);
                    if (neg < 0) closed = true;
                }
                if (!closed) {
                    pos = warp_find_pos(label, zidx, B, lane, lab_i, idx_i);
                } else {
                    if (i < k) { pos = (i == 0) ? 1 : 0;       neg = k; }
                    else       { pos = (i == k) ? (k + 1) : k; neg = 0; }
                    if (pos >= B || neg >= B || k < 2) pos = -1;
                }
                if (lane == 0) { s_pos[rid] = pos; s_neg[rid] = neg; }
            } else {
                if (lane == 0) { s_pos[rid] = -1; s_neg[rid] = -1; }
            }
        }
        __syncthreads();

        const int pos = s_pos[rid];
        const int neg = s_neg[rid];
        float sap = 0.0f, san = 0.0f;
        if (i < B && pos >= 0 && neg >= 0) {
            const float4* p = (const float4*)(z + (size_t)pos * 1024);
            if (neg == 0) {
                #pragma unroll
                for (int u = 0; u < 4; u++) {
                    const int v = base + lane + (u << 5);
                    float4 pv = __ldg(&p[v]);
                    float4 nv = s_n4[v];
                    float d;
                    d = av[u].x - pv.x + EPS_V; sap = fmaf(d, d, sap);
                    d = av[u].y - pv.y + EPS_V; sap = fmaf(d, d, sap);
                    d = av[u].z - pv.z + EPS_V; sap = fmaf(d, d, sap);
                    d = av[u].w - pv.w + EPS_V; sap = fmaf(d, d, sap);
                    d = av[u].x - nv.x + EPS_V; san = fmaf(d, d, san);
                    d = av[u].y - nv.y + EPS_V; san = fmaf(d, d, san);
                    d = av[u].z - nv.z + EPS_V; san = fmaf(d, d, san);
                    d = av[u].w - nv.w + EPS_V; san = fmaf(d, d, san);
                }
            } else {
                const float4* n = (const float4*)(z + (size_t)neg * 1024);
                #pragma unroll
                for (int u = 0; u < 4; u++) {
                    const int v = base + lane + (u << 5);
                    float4 pv = __ldg(&p[v]);
                    float4 nv = __ldg(&n[v]);
                    float d;
                    d = av[u].x - pv.x + EPS_V; sap = fmaf(d, d, sap);
                    d = av[u].y - pv.y + EPS_V; sap = fmaf(d, d, sap);
                    d = av[u].z - pv.z + EPS_V; sap = fmaf(d, d, sap);
                    d = av[u].w - pv.w + EPS_V; sap = fmaf(d, d, sap);
                    d = av[u].x - nv.x + EPS_V; san = fmaf(d, d, san);
                    d = av[u].y - nv.y + EPS_V; san = fmaf(d, d, san);
                    d = av[u].z - nv.z + EPS_V; san = fmaf(d, d, san);
                    d = av[u].w - nv.w + EPS_V; san = fmaf(d, d, san);
                }
            }
        }
        #pragma unroll
        for (int o = 16; o > 0; o >>= 1) {
            sap += __shfl_xor_sync(0xffffffffu, sap, o);
            san += __shfl_xor_sync(0xffffffffu, san, o);
        }
        if (lane == 0) { s_sap[warp] = sap; s_san[warp] = san; }
        __syncthreads();

        // ---- per-row combine (threads 0..3, all in warp 0) ----
        if (tid < 4) {
            const int r  = tid;
            const int ir = blockIdx.x * 4 + r;
            unsigned long long q = 0ull; unsigned int c = 0u;
            if (ir < B && s_pos[r] >= 0 && s_neg[r] >= 0) {
                float fap = s_sap[2 * r] + s_sap[2 * r + 1];
                float fan = s_san[2 * r] + s_san[2 * r + 1];
                float per = fmaxf(sqrtf(fap) - sqrtf(fan) + MARGIN, 0.0f);
                q = quant(per); c = 1u;
            }
            s_q[tid] = q; s_c[tid] = c;
        } else if (tid < 8) {
            s_q[tid] = 0ull; s_c[tid] = 0u;
        }
    } else {
        // ---- generic fallback (any C): one row per warp, grid-stride ----
        unsigned long long wq = 0ull; unsigned int wc = 0u;
        const int l0 = __ldg(&label[0]);
        for (int i = blockIdx.x * 8 + warp; i < B; i += gridDim.x * 8) {
            const int lab_i = __ldg(&label[i]);
            const int idx_i = __ldg(&zidx[i]);
            int pos = -1, neg = -1;
            bool closed = false;
            if (lab_i != l0) neg = 0;
            else { neg = warp_find_first_diff(label, B, lane, l0); if (neg < 0) closed = true; }
            if (!closed) pos = warp_find_pos(label, zidx, B, lane, lab_i, idx_i);
            else {
                if (i < k) { pos = (i == 0) ? 1 : 0;       neg = k; }
                else       { pos = (i == k) ? (k + 1) : k; neg = 0; }
                if (pos >= B || neg >= B || k < 2) pos = -1;
            }
            if (pos >= 0 && neg >= 0) {
                const float4* a = (const float4*)(z + (size_t)i * C);
                const float4* p = (const float4*)(z + (size_t)pos * C);
                const float4* n = (const float4*)(z + (size_t)neg * C);
                float sap = 0.0f, san = 0.0f;
                const int nvec = C >> 2;
                for (int v = lane; v < nvec; v += 32) {
                    float4 avv = a[v];
                    float4 pv = __ldg(&p[v]);
                    float4 nv = __ldg(&n[v]);
                    float d;
                    d = avv.x - pv.x + EPS_V; sap = fmaf(d, d, sap);
                    d = avv.y - pv.y + EPS_V; sap = fmaf(d, d, sap);
                    d = avv.z - pv.z + EPS_V; sap = fmaf(d, d, sap);
                    d = avv.w - pv.w + EPS_V; sap = fmaf(d, d, sap);
                    d = avv.x - nv.x + EPS_V; san = fmaf(d, d, san);
                    d = avv.y - nv.y + EPS_V; san = fmaf(d, d, san);
                    d = avv.z - nv.z + EPS_V; san = fmaf(d, d, san);
                    d = avv.w - nv.w + EPS_V; san = fmaf(d, d, san);
                }
                #pragma unroll
                for (int o = 16; o > 0; o >>= 1) {
                    sap += __shfl_xor_sync(0xffffffffu, sap, o);
                    san += __shfl_xor_sync(0xffffffffu, san, o);
                }
                float per = fmaxf(sqrtf(sap) - sqrtf(san) + MARGIN, 0.0f);
                wq += quant(per); wc++;
            }
        }
        if (lane == 0) { s_q[warp] = wq; s_c[warp] = wc; }
    }

    __syncthreads();
    if (tid == 0) {
        unsigned long long q = 0ull; unsigned int c = 0u;
        #pragma unroll
        for (int w = 0; w < 8; w++) { q += s_q[w]; c += s_c[w]; }
        unsigned long long val = q
                               | ((unsigned long long)c << CNT_SHIFT)
                               | (1ull << DONE_SHIFT);
        unsigned long long old = atomicAdd(&g_acc, val);   // relaxed, no fence
        if ((old >> DONE_SHIFT) == (unsigned long long)(nblocks - 1u)) {
            unsigned long long t = old + val;
            unsigned long long sq = t & SUM_MASK;
            unsigned int cc = (unsigned int)((t >> CNT_SHIFT) & CNT_MASK);
            out[0] = (cc > 0u) ? (float)(((double)sq / 65536.0) / (double)cc) : 0.0f;
            g_acc = 0ull;   // reset for next graph replay
        }
    }
}

extern "C" void kernel_launch(void* const* d_in, const int* in_sizes, int n_in,
                              void* d_out, int out_size) {
    const int* z_label = (const int*)d_in[0];
    const int* z_idx   = (const int*)d_in[1];
    const float* z     = (const float*)d_in[2];
    float* out = (float*)d_out;

    const int B = in_sizes[0];
    const int C = in_sizes[2] / B;
    int k = (int)((double)B * 0.01);
    if (k < 2) k = 2;

    unsigned int nblocks = (C == 1024) ? (unsigned int)((B + 3) / 4)
                                       : (unsigned int)((B + 7) / 8);
    triplet_kernel<<<nblocks, 256>>>(z, z_label, z_idx, out, B, C, k, nblocks);
}

// round 17
// speedup vs baseline: 1.1530x; 1.1530x over previous
#include <cuda_runtime.h>
#include <math.h>

#define MARGIN 0.2f
#define EPS_V  1e-6f

// Packed accumulator: bits[0:38) sum_q (fixed-point 2^16),
//                     bits[38:52) valid count, bits[52:64) done-block count.
#define CNT_SHIFT  38
#define DONE_SHIFT 52
#define SUM_MASK   ((1ull << CNT_SHIFT) - 1ull)
#define CNT_MASK   ((1ull << (DONE_SHIFT - CNT_SHIFT)) - 1ull)

// Only global state: zero-init at load; last block resets it each run.
__device__ unsigned long long g_acc;

__device__ __forceinline__ unsigned long long quant(float per) {
    return (unsigned long long)(unsigned int)(per * 65536.0f + 0.5f);
}

// ---------------------------------------------------------------------------
// Warp-collective: first j with label[j] != l0 (or -1 -> all same).
// ---------------------------------------------------------------------------
__device__ __forceinline__ int warp_find_first_diff(const int* __restrict__ label,
                                                    int B, int lane, int l0) {
    for (int base = 0; base < B; base += 128) {
        const int j0 = base + (lane << 2);
        unsigned sub = 0u;
        if (j0 + 3 < B) {
            int4 lv = *(const int4*)(label + j0);
            sub = (lv.x != l0 ? 1u : 0u) | (lv.y != l0 ? 2u : 0u)
                | (lv.z != l0 ? 4u : 0u) | (lv.w != l0 ? 8u : 0u);
        } else {
            #pragma unroll
            for (int t = 0; t < 4; t++) {
                int j = j0 + t;
                if (j < B && label[j] != l0) sub |= 1u << t;
            }
        }
        unsigned act = __ballot_sync(0xffffffffu, sub != 0u);
        if (act) {
            int src = __ffs(act) - 1;
            unsigned ssub = __shfl_sync(0xffffffffu, sub, src);
            return base + (src << 2) + (__ffs(ssub) - 1);
        }
    }
    return -1;
}

// ---------------------------------------------------------------------------
// Warp-collective: first j with label[j]==lab_i && zidx[j]!=idx_i (or -1).
// ---------------------------------------------------------------------------
__device__ __forceinline__ int warp_find_pos(const int* __restrict__ label,
                                             const int* __restrict__ zidx,
                                             int B, int lane, int lab_i, int idx_i) {
    for (int base = 0; base < B; base += 128) {
        const int j0 = base + (lane << 2);
        unsigned sub = 0u;
        if (j0 + 3 < B) {
            int4 lv = *(const int4*)(label + j0);
            sub = (lv.x == lab_i ? 1u : 0u) | (lv.y == lab_i ? 2u : 0u)
                | (lv.z == lab_i ? 4u : 0u) | (lv.w == lab_i ? 8u : 0u);
        } else {
            #pragma unroll
            for (int t = 0; t < 4; t++) {
                int j = j0 + t;
                if (j < B && label[j] == lab_i) sub |= 1u << t;
            }
        }
        while (true) {
            unsigned act = __ballot_sync(0xffffffffu, sub != 0u);
            if (!act) break;
            int src = __ffs(act) - 1;
            unsigned ssub = __shfl_sync(0xffffffffu, sub, src);
            int j = base + (src << 2) + (__ffs(ssub) - 1);
            if (__ldg(&zidx[j]) != idx_i) return j;   // broadcast load
            if (lane == src) sub &= (sub - 1u);
        }
    }
    return -1;
}

// Resolve (pos, neg) for row i; true if the triplet is valid.
__device__ __forceinline__ bool mine_row(const int* __restrict__ label,
                                         const int* __restrict__ zidx,
                                         int B, int k, int lane,
                                         int i, int l0,
                                         int& pos, int& neg) {
    const int lab_i = __ldg(&label[i]);
    const int idx_i = __ldg(&zidx[i]);
    pos = -1; neg = -1;
    bool closed = false;
    if (lab_i != l0) {
        neg = 0;
    } else {
        neg = warp_find_first_diff(label, B, lane, l0);
        if (neg < 0) closed = true;
    }
    if (!closed) {
        pos = warp_find_pos(label, zidx, B, lane, lab_i, idx_i);
    } else {
        if (i < k) { pos = (i == 0) ? 1 : 0;       neg = k; }
        else       { pos = (i == k) ? (k + 1) : k; neg = 0; }
        if (pos >= B || neg >= B || k < 2) pos = -1;
    }
    return (pos >= 0) && (neg >= 0);
}

// Distance body: a from registers, neg from SMEM row-0 (hot) or LDG.
__device__ __forceinline__ float dist_regs(const float4* __restrict__ av_regs_end, // av[8]
                                           const float4 av[8],
                                           const float* __restrict__ z,
                                           const float4* __restrict__ s_n4,
                                           int lane, int pos, int neg) {
    const float4* p = (const float4*)(z + (size_t)pos * 1024);
    float sap = 0.0f, san = 0.0f;
    if (neg == 0) {
        #pragma unroll
        for (int u = 0; u < 8; u++) {
            const int v = lane + (u << 5);
            float4 pv = __ldg(&p[v]);
            float4 nv = s_n4[v];
            float d;
            d = av[u].x - pv.x + EPS_V; sap = fmaf(d, d, sap);
            d = av[u].y - pv.y + EPS_V; sap = fmaf(d, d, sap);
            d = av[u].z - pv.z + EPS_V; sap = fmaf(d, d, sap);
            d = av[u].w - pv.w + EPS_V; sap = fmaf(d, d, sap);
            d = av[u].x - nv.x + EPS_V; san = fmaf(d, d, san);
            d = av[u].y - nv.y + EPS_V; san = fmaf(d, d, san);
            d = av[u].z - nv.z + EPS_V; san = fmaf(d, d, san);
            d = av[u].w - nv.w + EPS_V; san = fmaf(d, d, san);
        }
    } else {
        const float4* n = (const float4*)(z + (size_t)neg * 1024);
        #pragma unroll
        for (int u = 0; u < 8; u++) {
            const int v = lane + (u << 5);
            float4 pv = __ldg(&p[v]);
            float4 nv = __ldg(&n[v]);
            float d;
            d = av[u].x - pv.x + EPS_V; sap = fmaf(d, d, sap);
            d = av[u].y - pv.y + EPS_V; sap = fmaf(d, d, sap);
            d = av[u].z - pv.z + EPS_V; sap = fmaf(d, d, sap);
            d = av[u].w - pv.w + EPS_V; sap = fmaf(d, d, sap);
            d = av[u].x - nv.x + EPS_V; san = fmaf(d, d, san);
            d = av[u].y - nv.y + EPS_V; san = fmaf(d, d, san);
            d = av[u].z - nv.z + EPS_V; san = fmaf(d, d, san);
            d = av[u].w - nv.w + EPS_V; san = fmaf(d, d, san);
        }
    }
    #pragma unroll
    for (int o = 16; o > 0; o >>= 1) {
        sap += __shfl_xor_sync(0xffffffffu, sap, o);
        san += __shfl_xor_sync(0xffffffffu, san, o);
    }
    return fmaxf(sqrtf(sap) - sqrtf(san) + MARGIN, 0.0f);
}

// ---------------------------------------------------------------------------
// Fast path (C==1024, B%16==0): grid = B/16 = single wave. Each warp: row r0
// in registers (8 LDG.128), row r1 via cp.async.cg into its SMEM slot — both
// streams issued back-to-back (8KB in flight/warp). Mine r0, compute r0,
// mine r1, wait cp.async (already done), compute r1 from LDS. Row 0 (neg)
// staged once per block. Tail = one packed relaxed atomicAdd (no fences).
// ---------------------------------------------------------------------------
__global__ void __launch_bounds__(256) triplet_kernel(const float* __restrict__ z,
                                                      const int* __restrict__ label,
                                                      const int* __restrict__ zidx,
                                                      float* __restrict__ out,
                                                      int B, int C, int k,
                                                      unsigned int nblocks, int fast) {
    __shared__ float4 s_n4[256];        // row 0 (neg) staging: 4 KB
    __shared__ float  s_r1[8 * 1024];   // per-warp row r1 staging: 32 KB
    __shared__ unsigned long long s_q[8];
    __shared__ unsigned int      s_c[8];

    const int tid  = threadIdx.x;
    const int warp = tid >> 5;
    const int lane = tid & 31;

    unsigned long long wq = 0ull;
    unsigned int       wc = 0u;

    if (fast) {
        const int r0 = blockIdx.x * 16 + warp;
        const int r1 = r0 + 8;

        // ---- stream row r1 into SMEM (cp.async.cg: no regs, L1-bypass) ----
        {
            const char* g1 = (const char*)(z + (size_t)r1 * 1024);
            unsigned int sb = (unsigned int)__cvta_generic_to_shared(&s_r1[warp * 1024]);
            #pragma unroll
            for (int u = 0; u < 8; u++) {
                unsigned int sa = sb + (unsigned int)((lane + (u << 5)) * 16);
                asm volatile("cp.async.cg.shared.global [%0], [%1], 16;\n"
                             :: "r"(sa), "l"(g1 + (lane + (u << 5)) * 16));
            }
            asm volatile("cp.async.commit_group;\n" ::: "memory");
        }

        // ---- row r0 into registers (8 back-to-back LDG.128) ----
        float4 av[8];
        {
            const float4* a0 = (const float4*)(z + (size_t)r0 * 1024);
            #pragma unroll
            for (int u = 0; u < 8; u++)
                av[u] = a0[lane + (u << 5)];
        }

        // ---- stage row 0 (neg row for ~255/256 of samples) ----
        s_n4[tid] = __ldg(&((const float4*)z)[tid]);
        __syncthreads();

        const int l0 = __ldg(&label[0]);

        // ---- row r0: mine + compute (a in regs) ----
        {
            int pos, neg;
            if (mine_row(label, zidx, B, k, lane, r0, l0, pos, neg)) {
                float per = dist_regs(nullptr, av, z, s_n4, lane, pos, neg);
                wq += quant(per); wc++;
            }
        }

        // ---- row r1: mine, then consume the cp.async data from SMEM ----
        {
            int pos, neg;
            bool v = mine_row(label, zidx, B, k, lane, r1, l0, pos, neg);
            asm volatile("cp.async.wait_group 0;\n" ::: "memory");
            if (v) {
                const float4* a1 = (const float4*)&s_r1[warp * 1024];
                const float4* p  = (const float4*)(z + (size_t)pos * 1024);
                float sap = 0.0f, san = 0.0f;
                if (neg == 0) {
                    #pragma unroll
                    for (int u = 0; u < 8; u++) {
                        const int v4 = lane + (u << 5);
                        float4 A = a1[v4];
                        float4 pv = __ldg(&p[v4]);
                        float4 nv = s_n4[v4];
                        float d;
                        d = A.x - pv.x + EPS_V; sap = fmaf(d, d, sap);
                        d = A.y - pv.y + EPS_V; sap = fmaf(d, d, sap);
                        d = A.z - pv.z + EPS_V; sap = fmaf(d, d, sap);
                        d = A.w - pv.w + EPS_V; sap = fmaf(d, d, sap);
                        d = A.x - nv.x + EPS_V; san = fmaf(d, d, san);
                        d = A.y - nv.y + EPS_V; san = fmaf(d, d, san);
                        d = A.z - nv.z + EPS_V; san = fmaf(d, d, san);
                        d = A.w - nv.w + EPS_V; san = fmaf(d, d, san);
                    }
                } else {
                    const float4* n = (const float4*)(z + (size_t)neg * 1024);
                    #pragma unroll
                    for (int u = 0; u < 8; u++) {
                        const int v4 = lane + (u << 5);
                        float4 A = a1[v4];
                        float4 pv = __ldg(&p[v4]);
                        float4 nv = __ldg(&n[v4]);
                        float d;
                        d = A.x - pv.x + EPS_V; sap = fmaf(d, d, sap);
                        d = A.y - pv.y + EPS_V; sap = fmaf(d, d, sap);
                        d = A.z - pv.z + EPS_V; sap = fmaf(d, d, sap);
                        d = A.w - pv.w + EPS_V; sap = fmaf(d, d, sap);
                        d = A.x - nv.x + EPS_V; san = fmaf(d, d, san);
                        d = A.y - nv.y + EPS_V; san = fmaf(d, d, san);
                        d = A.z - nv.z + EPS_V; san = fmaf(d, d, san);
                        d = A.w - nv.w + EPS_V; san = fmaf(d, d, san);
                    }
                }
                #pragma unroll
                for (int o = 16; o > 0; o >>= 1) {
                    sap += __shfl_xor_sync(0xffffffffu, sap, o);
                    san += __shfl_xor_sync(0xffffffffu, san, o);
                }
                float per = fmaxf(sqrtf(sap) - sqrtf(san) + MARGIN, 0.0f);
                wq += quant(per); wc++;
            }
        }
    } else {
        // ---- generic fallback (any C / any B): one row per warp ----
        const int l0 = __ldg(&label[0]);
        for (int i = blockIdx.x * 8 + warp; i < B; i += gridDim.x * 8) {
            int pos, neg;
            if (!mine_row(label, zidx, B, k, lane, i, l0, pos, neg)) continue;
            const float4* a = (const float4*)(z + (size_t)i * C);
            const float4* p = (const float4*)(z + (size_t)pos * C);
            const float4* n = (const float4*)(z + (size_t)neg * C);
            float sap = 0.0f, san = 0.0f;
            const int nvec = C >> 2;
            for (int v = lane; v < nvec; v += 32) {
                float4 avv = a[v];
                float4 pv = __ldg(&p[v]);
                float4 nv = __ldg(&n[v]);
                float d;
                d = avv.x - pv.x + EPS_V; sap = fmaf(d, d, sap);
                d = avv.y - pv.y + EPS_V; sap = fmaf(d, d, sap);
                d = avv.z - pv.z + EPS_V; sap = fmaf(d, d, sap);
                d = avv.w - pv.w + EPS_V; sap = fmaf(d, d, sap);
                d = avv.x - nv.x + EPS_V; san = fmaf(d, d, san);
                d = avv.y - nv.y + EPS_V; san = fmaf(d, d, san);
                d = avv.z - nv.z + EPS_V; san = fmaf(d, d, san);
                d = avv.w - nv.w + EPS_V; san = fmaf(d, d, san);
            }
            #pragma unroll
            for (int o = 16; o > 0; o >>= 1) {
                sap += __shfl_xor_sync(0xffffffffu, sap, o);
                san += __shfl_xor_sync(0xffffffffu, san, o);
            }
            float per = fmaxf(sqrtf(sap) - sqrtf(san) + MARGIN, 0.0f);
            wq += quant(per); wc++;
        }
    }

    // ---- single-atomic deterministic tail ----
    if (lane == 0) { s_q[warp] = wq; s_c[warp] = wc; }
    __syncthreads();
    if (tid == 0) {
        unsigned long long q = 0ull; unsigned int c = 0u;
        #pragma unroll
        for (int w = 0; w < 8; w++) { q += s_q[w]; c += s_c[w]; }
        unsigned long long val = q
                               | ((unsigned long long)c << CNT_SHIFT)
                               | (1ull << DONE_SHIFT);
        unsigned long long old = atomicAdd(&g_acc, val);   // relaxed, no fence
        if ((old >> DONE_SHIFT) == (unsigned long long)(nblocks - 1u)) {
            unsigned long long t = old + val;
            unsigned long long sq = t & SUM_MASK;
            unsigned int cc = (unsigned int)((t >> CNT_SHIFT) & CNT_MASK);
            out[0] = (cc > 0u) ? (float)(((double)sq / 65536.0) / (double)cc) : 0.0f;
            g_acc = 0ull;   // reset for next graph replay
        }
    }
}

extern "C" void kernel_launch(void* const* d_in, const int* in_sizes, int n_in,
                              void* d_out, int out_size) {
    const int* z_label = (const int*)d_in[0];
    const int* z_idx   = (const int*)d_in[1];
    const float* z     = (const float*)d_in[2];
    float* out = (float*)d_out;

    const int B = in_sizes[0];
    const int C = in_sizes[2] / B;
    int k = (int)((double)B * 0.01);
    if (k < 2) k = 2;

    const int fast = (C == 1024 && (B % 16) == 0) ? 1 : 0;
    unsigned int nblocks = fast ? (unsigned int)(B / 16)
                                : (unsigned int)((B + 7) / 8);
    triplet_kernel<<<nblocks, 256>>>(z, z_label, z_idx, out, B, C, k, nblocks, fast);
}